// round 1
// baseline (speedup 1.0000x reference)
#include <cuda_runtime.h>
#include <cstdint>

#define U_NUM 30000
#define NTOT  100000

typedef unsigned long long u64;

// ---------------- scratch (device globals; allocation-free) ----------------
__device__ float g_H0[(size_t)NTOT * 128];  // layer0: G1+G2
__device__ float g_F1[(size_t)NTOT * 128];  // layer0: G1+bias -> scatter target -> feat1
__device__ float g_H1[(size_t)NTOT * 64];   // layer1: G1+G2
__device__ float g_F2[(size_t)NTOT * 64];   // layer1: G1+bias -> scatter target -> feat2

// ---------------- packed f32x2 helpers ----------------
__device__ __forceinline__ u64 pack2(float lo, float hi) {
    u64 v; asm("mov.b64 %0, {%1, %2};" : "=l"(v) : "f"(lo), "f"(hi)); return v;
}
__device__ __forceinline__ void unpack2(u64 v, float& lo, float& hi) {
    asm("mov.b64 {%0, %1}, %2;" : "=f"(lo), "=f"(hi) : "l"(v));
}
__device__ __forceinline__ u64 fma2(u64 a, u64 b, u64 c) {
    u64 d; asm("fma.rn.f32x2 %0, %1, %2, %3;" : "=l"(d) : "l"(a), "l"(b), "l"(c)); return d;
}
__device__ __forceinline__ u64 mul2(u64 a, u64 b) {
    u64 d; asm("mul.rn.f32x2 %0, %1, %2;" : "=l"(d) : "l"(a), "l"(b)); return d;
}
__device__ __forceinline__ void red4(float* p, float a, float b, float c, float d) {
    asm volatile("{ .reg .u64 q; cvta.to.global.u64 q, %0; red.global.add.v4.f32 [q], {%1,%2,%3,%4}; }"
                 :: "l"(p), "f"(a), "f"(b), "f"(c), "f"(d) : "memory");
}

// ============================================================================
// Layer 0 fused GEMM: A[N,256] (concat uE|iE, gathered by row) ->
//   g_F1[r,c] = (A@W1^T)[r,c] + b1[c]+b2[c]
//   g_H0[r,c] = (A@W1^T + (A*A)@W2^T)[r,c]
// BM=64, BN=128(=full Dout), BK=16, 256 thr, thread tile 4x8 (f32x2-packed 4x4)
// ============================================================================
__global__ __launch_bounds__(256) void k_gemm0(
    const float* __restrict__ uE, const float* __restrict__ iE,
    const float* __restrict__ W1, const float* __restrict__ W2,
    const float* __restrict__ b1, const float* __restrict__ b2)
{
    __shared__ float As[16][68];
    __shared__ float B1s[16][128];
    __shared__ float B2s[16][128];
    const int t = threadIdx.x;
    const int row0 = blockIdx.x * 64;
    const int ty = t >> 4, tx = t & 15;

    u64 acc1[4][4], acc2[4][4];
#pragma unroll
    for (int i = 0; i < 4; i++)
#pragma unroll
        for (int j = 0; j < 4; j++) { acc1[i][j] = 0ull; acc2[i][j] = 0ull; }

    const int ar = row0 + (t >> 2);
    const int ak = (t & 3) * 4;
    const float* abase = nullptr;
    if (ar < NTOT)
        abase = (ar < U_NUM) ? (uE + (size_t)ar * 256)
                             : (iE + (size_t)(ar - U_NUM) * 256);

    for (int k0 = 0; k0 < 256; k0 += 16) {
        float4 av = make_float4(0.f, 0.f, 0.f, 0.f);
        if (abase) av = *(const float4*)(abase + k0 + ak);
        float4 w1v[2], w2v[2];
#pragma unroll
        for (int i = 0; i < 2; i++) {
            int idx = t + i * 256;
            int c = idx >> 2, kq = (idx & 3) * 4;
            w1v[i] = *(const float4*)(W1 + (size_t)c * 256 + k0 + kq);
            w2v[i] = *(const float4*)(W2 + (size_t)c * 256 + k0 + kq);
        }
        __syncthreads();
        {
            int r = t >> 2;
            As[ak + 0][r] = av.x; As[ak + 1][r] = av.y;
            As[ak + 2][r] = av.z; As[ak + 3][r] = av.w;
        }
#pragma unroll
        for (int i = 0; i < 2; i++) {
            int idx = t + i * 256;
            int c = idx >> 2, kq = (idx & 3) * 4;
            B1s[kq + 0][c] = w1v[i].x; B1s[kq + 1][c] = w1v[i].y;
            B1s[kq + 2][c] = w1v[i].z; B1s[kq + 3][c] = w1v[i].w;
            B2s[kq + 0][c] = w2v[i].x; B2s[kq + 1][c] = w2v[i].y;
            B2s[kq + 2][c] = w2v[i].z; B2s[kq + 3][c] = w2v[i].w;
        }
        __syncthreads();
#pragma unroll
        for (int k = 0; k < 16; k++) {
            float4 af = *(const float4*)&As[k][ty * 4];
            u64 ad[4], a2d[4];
            ad[0] = pack2(af.x, af.x); ad[1] = pack2(af.y, af.y);
            ad[2] = pack2(af.z, af.z); ad[3] = pack2(af.w, af.w);
#pragma unroll
            for (int i = 0; i < 4; i++) a2d[i] = mul2(ad[i], ad[i]);
            ulonglong2 p1 = *(const ulonglong2*)&B1s[k][tx * 8];
            ulonglong2 q1 = *(const ulonglong2*)&B1s[k][tx * 8 + 4];
            ulonglong2 p2 = *(const ulonglong2*)&B2s[k][tx * 8];
            ulonglong2 q2 = *(const ulonglong2*)&B2s[k][tx * 8 + 4];
            u64 bb1[4] = {p1.x, p1.y, q1.x, q1.y};
            u64 bb2[4] = {p2.x, p2.y, q2.x, q2.y};
#pragma unroll
            for (int i = 0; i < 4; i++)
#pragma unroll
                for (int j = 0; j < 4; j++) {
                    acc1[i][j] = fma2(ad[i],  bb1[j], acc1[i][j]);
                    acc2[i][j] = fma2(a2d[i], bb2[j], acc2[i][j]);
                }
        }
    }

    float bias[8];
#pragma unroll
    for (int j = 0; j < 8; j++) bias[j] = b1[tx * 8 + j] + b2[tx * 8 + j];
#pragma unroll
    for (int i = 0; i < 4; i++) {
        int r = row0 + ty * 4 + i;
        if (r < NTOT) {
            float* f1p = g_F1 + (size_t)r * 128 + tx * 8;
            float* h0p = g_H0 + (size_t)r * 128 + tx * 8;
#pragma unroll
            for (int j = 0; j < 4; j++) {
                float g1lo, g1hi, g2lo, g2hi;
                unpack2(acc1[i][j], g1lo, g1hi);
                unpack2(acc2[i][j], g2lo, g2hi);
                f1p[2 * j]     = g1lo + bias[2 * j];
                f1p[2 * j + 1] = g1hi + bias[2 * j + 1];
                h0p[2 * j]     = g1lo + g2lo;
                h0p[2 * j + 1] = g1hi + g2hi;
            }
        }
    }
}

// ============================================================================
// Layer 1 fused GEMM: A = g_F1 [N,128] -> g_F2 (G1+bias), g_H1 (G1+G2), Dout=64
// BM=64, BN=64, BK=16, 256 thr, thread tile 4x4 (packed 4x2)
// ============================================================================
__global__ __launch_bounds__(256) void k_gemm1(
    const float* __restrict__ W1, const float* __restrict__ W2,
    const float* __restrict__ b1, const float* __restrict__ b2)
{
    __shared__ float As[16][68];
    __shared__ float B1s[16][64];
    __shared__ float B2s[16][64];
    const int t = threadIdx.x;
    const int row0 = blockIdx.x * 64;
    const int ty = t >> 4, tx = t & 15;

    u64 acc1[4][2], acc2[4][2];
#pragma unroll
    for (int i = 0; i < 4; i++)
#pragma unroll
        for (int j = 0; j < 2; j++) { acc1[i][j] = 0ull; acc2[i][j] = 0ull; }

    const int ar = row0 + (t >> 2);
    const int ak = (t & 3) * 4;
    const float* abase = (ar < NTOT) ? (g_F1 + (size_t)ar * 128) : nullptr;
    const int bc = t >> 2, bk = (t & 3) * 4;

    for (int k0 = 0; k0 < 128; k0 += 16) {
        float4 av = make_float4(0.f, 0.f, 0.f, 0.f);
        if (abase) av = *(const float4*)(abase + k0 + ak);
        float4 w1v = *(const float4*)(W1 + (size_t)bc * 128 + k0 + bk);
        float4 w2v = *(const float4*)(W2 + (size_t)bc * 128 + k0 + bk);
        __syncthreads();
        {
            int r = t >> 2;
            As[ak + 0][r] = av.x; As[ak + 1][r] = av.y;
            As[ak + 2][r] = av.z; As[ak + 3][r] = av.w;
        }
        B1s[bk + 0][bc] = w1v.x; B1s[bk + 1][bc] = w1v.y;
        B1s[bk + 2][bc] = w1v.z; B1s[bk + 3][bc] = w1v.w;
        B2s[bk + 0][bc] = w2v.x; B2s[bk + 1][bc] = w2v.y;
        B2s[bk + 2][bc] = w2v.z; B2s[bk + 3][bc] = w2v.w;
        __syncthreads();
#pragma unroll
        for (int k = 0; k < 16; k++) {
            float4 af = *(const float4*)&As[k][ty * 4];
            u64 ad[4], a2d[4];
            ad[0] = pack2(af.x, af.x); ad[1] = pack2(af.y, af.y);
            ad[2] = pack2(af.z, af.z); ad[3] = pack2(af.w, af.w);
#pragma unroll
            for (int i = 0; i < 4; i++) a2d[i] = mul2(ad[i], ad[i]);
            ulonglong2 p1 = *(const ulonglong2*)&B1s[k][tx * 4];
            ulonglong2 p2 = *(const ulonglong2*)&B2s[k][tx * 4];
            u64 bb1[2] = {p1.x, p1.y};
            u64 bb2[2] = {p2.x, p2.y};
#pragma unroll
            for (int i = 0; i < 4; i++)
#pragma unroll
                for (int j = 0; j < 2; j++) {
                    acc1[i][j] = fma2(ad[i],  bb1[j], acc1[i][j]);
                    acc2[i][j] = fma2(a2d[i], bb2[j], acc2[i][j]);
                }
        }
    }

    float bias[4];
#pragma unroll
    for (int j = 0; j < 4; j++) bias[j] = b1[tx * 4 + j] + b2[tx * 4 + j];
#pragma unroll
    for (int i = 0; i < 4; i++) {
        int r = row0 + ty * 4 + i;
        if (r < NTOT) {
            float* f2p = g_F2 + (size_t)r * 64 + tx * 4;
            float* h1p = g_H1 + (size_t)r * 64 + tx * 4;
#pragma unroll
            for (int j = 0; j < 2; j++) {
                float g1lo, g1hi, g2lo, g2hi;
                unpack2(acc1[i][j], g1lo, g1hi);
                unpack2(acc2[i][j], g2lo, g2hi);
                f2p[2 * j]     = g1lo + bias[2 * j];
                f2p[2 * j + 1] = g1hi + bias[2 * j + 1];
                h1p[2 * j]     = g1lo + g2lo;
                h1p[2 * j + 1] = g1hi + g2hi;
            }
        }
    }
}

// ============================================================================
// SpMM scatter: F[row] += val * H[col]   (one warp per edge, D=128)
// ============================================================================
__global__ void k_spmm128(const int* __restrict__ er, const int* __restrict__ ec,
                          const float* __restrict__ ev, int nnz)
{
    int w = (blockIdx.x * blockDim.x + threadIdx.x) >> 5;
    int lane = threadIdx.x & 31;
    if (w >= nnz) return;
    int r = __ldg(er + w), c = __ldg(ec + w);
    float v = __ldg(ev + w);
    float4 x = *(const float4*)(g_H0 + (size_t)c * 128 + lane * 4);
    red4(g_F1 + (size_t)r * 128 + lane * 4, v * x.x, v * x.y, v * x.z, v * x.w);
}

// half-warp per edge, D=64
__global__ void k_spmm64(const int* __restrict__ er, const int* __restrict__ ec,
                         const float* __restrict__ ev, int nnz)
{
    int idx = blockIdx.x * blockDim.x + threadIdx.x;
    int e = idx >> 4;
    int l = idx & 15;
    if (e >= nnz) return;
    int r = __ldg(er + e), c = __ldg(ec + e);
    float v = __ldg(ev + e);
    float4 x = *(const float4*)(g_H1 + (size_t)c * 64 + l * 4);
    red4(g_F2 + (size_t)r * 64 + l * 4, v * x.x, v * x.y, v * x.z, v * x.w);
}

// ============================================================================
// Fused MLP: gather final[448] for user & item (896 cols), 896->64 relu,
// 64->32 relu, 32->1. One block = 64 batch rows, 256 threads.
// ============================================================================
__global__ __launch_bounds__(256) void k_mlp(
    const int* __restrict__ uIdx, const int* __restrict__ itIdx,
    const float* __restrict__ uE, const float* __restrict__ iE,
    const float* __restrict__ T1W, const float* __restrict__ T1b,
    const float* __restrict__ T2W, const float* __restrict__ T2b,
    const float* __restrict__ T3W, const float* __restrict__ T3b,
    float* __restrict__ out, int B)
{
    __shared__ float As[32][68];
    __shared__ float Bs[32][64];
    __shared__ float Hs[64][65];
    __shared__ float T2s[32][64];
    __shared__ int   su[64], si[64];
    __shared__ float part[4][64];

    const int t = threadIdx.x;
    const int rb = blockIdx.x * 64;
    if (t < 64) {
        int br = rb + t;
        su[t] = (br < B) ? uIdx[br] : 0;
        si[t] = (br < B) ? itIdx[br] : 0;
    }
#pragma unroll
    for (int i = 0; i < 2; i++) {
        int idx = t + i * 256;   // 512 float4 = 2048 floats = 32x64
        ((float4*)&T2s[0][0])[idx] = ((const float4*)T2W)[idx];
    }
    __syncthreads();

    const int ty = t >> 4, tx = t & 15;
    u64 acc[4][2];
#pragma unroll
    for (int i = 0; i < 4; i++) { acc[i][0] = 0ull; acc[i][1] = 0ull; }

    for (int kc = 0; kc < 28; kc++) {
        int kb = kc * 32;
        const float* src; int stride, off, radd; bool useU;
        if      (kb < 256) { src = uE;   stride = 256; off = kb;       useU = true;  radd = 0; }
        else if (kb < 384) { src = g_F1; stride = 128; off = kb - 256; useU = true;  radd = 0; }
        else if (kb < 448) { src = g_F2; stride = 64;  off = kb - 384; useU = true;  radd = 0; }
        else if (kb < 704) { src = iE;   stride = 256; off = kb - 448; useU = false; radd = 0; }
        else if (kb < 832) { src = g_F1; stride = 128; off = kb - 704; useU = false; radd = U_NUM; }
        else               { src = g_F2; stride = 64;  off = kb - 832; useU = false; radd = U_NUM; }
        __syncthreads();
#pragma unroll
        for (int i = 0; i < 2; i++) {
            int idx = t + i * 256;
            int r = idx >> 3, kq = (idx & 7) * 4;
            int rowi = (useU ? su[r] : si[r]) + radd;
            float4 a = *(const float4*)(src + (size_t)rowi * stride + off + kq);
            As[kq + 0][r] = a.x; As[kq + 1][r] = a.y;
            As[kq + 2][r] = a.z; As[kq + 3][r] = a.w;
            float4 wv = *(const float4*)(T1W + (size_t)r * 896 + kb + kq);
            Bs[kq + 0][r] = wv.x; Bs[kq + 1][r] = wv.y;
            Bs[kq + 2][r] = wv.z; Bs[kq + 3][r] = wv.w;
        }
        __syncthreads();
#pragma unroll
        for (int k = 0; k < 32; k++) {
            float4 af = *(const float4*)&As[k][ty * 4];
            u64 ad[4];
            ad[0] = pack2(af.x, af.x); ad[1] = pack2(af.y, af.y);
            ad[2] = pack2(af.z, af.z); ad[3] = pack2(af.w, af.w);
            ulonglong2 bp = *(const ulonglong2*)&Bs[k][tx * 4];
#pragma unroll
            for (int i = 0; i < 4; i++) {
                acc[i][0] = fma2(ad[i], bp.x, acc[i][0]);
                acc[i][1] = fma2(ad[i], bp.y, acc[i][1]);
            }
        }
    }

    // layer-1 epilogue: relu(acc + T1b) -> Hs
    float t1bv[4];
#pragma unroll
    for (int j = 0; j < 4; j++) t1bv[j] = T1b[tx * 4 + j];
#pragma unroll
    for (int i = 0; i < 4; i++) {
#pragma unroll
        for (int j = 0; j < 2; j++) {
            float lo, hi;
            unpack2(acc[i][j], lo, hi);
            Hs[ty * 4 + i][tx * 4 + 2 * j]     = fmaxf(lo + t1bv[2 * j], 0.f);
            Hs[ty * 4 + i][tx * 4 + 2 * j + 1] = fmaxf(hi + t1bv[2 * j + 1], 0.f);
        }
    }
    __syncthreads();

    // layers 2+3
    {
        int r = t & 63, g = t >> 6;
        float p = 0.f;
#pragma unroll
        for (int j = 0; j < 8; j++) {
            int c2 = g * 8 + j;
            float s = T2b[c2];
#pragma unroll
            for (int k = 0; k < 64; k++) s += Hs[r][k] * T2s[c2][k];
            s = fmaxf(s, 0.f);
            p += s * T3W[c2];
        }
        part[g][r] = p;
    }
    __syncthreads();
    if (t < 64) {
        int br = rb + t;
        if (br < B)
            out[br] = part[0][t] + part[1][t] + part[2][t] + part[3][t] + T3b[0];
    }
}

// ============================================================================
extern "C" void kernel_launch(void* const* d_in, const int* in_sizes, int n_in,
                              void* d_out, int out_size)
{
    const int*   userIdx = (const int*)d_in[0];
    const int*   itemIdx = (const int*)d_in[1];
    const int*   er      = (const int*)d_in[2];
    const int*   ec      = (const int*)d_in[3];
    const float* ev      = (const float*)d_in[4];
    const float* uE      = (const float*)d_in[5];
    const float* iE      = (const float*)d_in[6];
    const float* W1_0    = (const float*)d_in[7];
    const float* b1_0    = (const float*)d_in[8];
    const float* W2_0    = (const float*)d_in[9];
    const float* b2_0    = (const float*)d_in[10];
    const float* W1_1    = (const float*)d_in[11];
    const float* b1_1    = (const float*)d_in[12];
    const float* W2_1    = (const float*)d_in[13];
    const float* b2_1    = (const float*)d_in[14];
    const float* T1W     = (const float*)d_in[15];
    const float* T1b     = (const float*)d_in[16];
    const float* T2W     = (const float*)d_in[17];
    const float* T2b     = (const float*)d_in[18];
    const float* T3W     = (const float*)d_in[19];
    const float* T3b     = (const float*)d_in[20];
    float* out = (float*)d_out;

    const int B   = in_sizes[0];
    const int nnz = in_sizes[2];

    const int gemmBlocks = (NTOT + 63) / 64;

    k_gemm0<<<gemmBlocks, 256>>>(uE, iE, W1_0, W2_0, b1_0, b2_0);

    {
        long long thr = (long long)nnz * 32;
        int blocks = (int)((thr + 255) / 256);
        k_spmm128<<<blocks, 256>>>(er, ec, ev, nnz);
    }

    k_gemm1<<<gemmBlocks, 256>>>(W1_1, W2_1, b1_1, b2_1);

    {
        long long thr = (long long)nnz * 16;
        int blocks = (int)((thr + 255) / 256);
        k_spmm64<<<blocks, 256>>>(er, ec, ev, nnz);
    }

    k_mlp<<<(B + 63) / 64, 256>>>(userIdx, itemIdx, uE, iE,
                                  T1W, T1b, T2W, T2b, T3W, T3b, out, B);
}

// round 3
// speedup vs baseline: 2.2123x; 2.2123x over previous
#include <cuda_runtime.h>
#include <cuda_bf16.h>
#include <cstdint>

#define U_NUM 30000
#define NTOT  100000

typedef unsigned long long u64;
typedef unsigned int u32;

// ---------------- scratch (device globals; allocation-free) ----------------
__device__ __align__(256) float g_H0[(size_t)NTOT * 128];
__device__ __align__(256) float g_F1[(size_t)NTOT * 128];
__device__ __align__(256) float g_H1[(size_t)NTOT * 64];
__device__ __align__(256) float g_F2[(size_t)NTOT * 64];
// fragment-packed bf16 weights: [v(hi=0,lo=1)][ks][nt][lane] as uint2
__device__ __align__(256) uint2 g_w10f[2 * 16 * 16 * 32];
__device__ __align__(256) uint2 g_w20f[2 * 16 * 16 * 32];
__device__ __align__(256) uint2 g_w11f[2 * 8 * 8 * 32];
__device__ __align__(256) uint2 g_w21f[2 * 8 * 8 * 32];

// ---------------- helpers ----------------
__device__ __forceinline__ u32 smem_u32(const void* p) {
    u32 a;
    asm("{ .reg .u64 t; cvta.to.shared.u64 t, %1; cvt.u32.u64 %0, t; }" : "=r"(a) : "l"(p));
    return a;
}
__device__ __forceinline__ void ldm4(u32* r, u32 addr) {
    asm volatile("ldmatrix.sync.aligned.m8n8.x4.shared.b16 {%0,%1,%2,%3}, [%4];"
                 : "=r"(r[0]), "=r"(r[1]), "=r"(r[2]), "=r"(r[3]) : "r"(addr));
}
__device__ __forceinline__ void mma16816(float* c, const u32* a, uint2 b) {
    asm volatile("mma.sync.aligned.m16n8k16.row.col.f32.bf16.bf16.f32 "
                 "{%0,%1,%2,%3}, {%4,%5,%6,%7}, {%8,%9}, {%0,%1,%2,%3};"
                 : "+f"(c[0]), "+f"(c[1]), "+f"(c[2]), "+f"(c[3])
                 : "r"(a[0]), "r"(a[1]), "r"(a[2]), "r"(a[3]), "r"(b.x), "r"(b.y));
}
__device__ __forceinline__ void split2(float a, float b, u32& hi, u32& lo) {
    __nv_bfloat162 h = __floats2bfloat162_rn(a, b);
    float2 hf = __bfloat1622float2(h);
    __nv_bfloat162 l = __floats2bfloat162_rn(a - hf.x, b - hf.y);
    hi = *reinterpret_cast<u32*>(&h);
    lo = *reinterpret_cast<u32*>(&l);
}
// packed f32x2 helpers (mlp)
__device__ __forceinline__ u64 pack2(float lo, float hi) {
    u64 v; asm("mov.b64 %0, {%1, %2};" : "=l"(v) : "f"(lo), "f"(hi)); return v;
}
__device__ __forceinline__ void unpack2(u64 v, float& lo, float& hi) {
    asm("mov.b64 {%0, %1}, %2;" : "=f"(lo), "=f"(hi) : "l"(v));
}
__device__ __forceinline__ u64 fma2(u64 a, u64 b, u64 c) {
    u64 d; asm("fma.rn.f32x2 %0, %1, %2, %3;" : "=l"(d) : "l"(a), "l"(b), "l"(c)); return d;
}
__device__ __forceinline__ void red4(float* p, float a, float b, float c, float d) {
    asm volatile("{ .reg .u64 q; cvta.to.global.u64 q, %0; red.global.add.v4.f32 [q], {%1,%2,%3,%4}; }"
                 :: "l"(p), "f"(a), "f"(b), "f"(c), "f"(d) : "memory");
}

// ============================================================================
// Weight fragment prep: W[DOUT][K] fp32 -> hi/lo bf16 in mma B-fragment order
// ============================================================================
__device__ __forceinline__ void pack_frag(const float* __restrict__ W, uint2* __restrict__ dst,
                                          int ks, int nt, int lane, int KS, int NT, int K)
{
    int n = nt * 8 + (lane >> 2);
    int k = ks * 16 + (lane & 3) * 2;
    const float* p = W + (size_t)n * K + k;
    float x0 = p[0], x1 = p[1], x2 = p[8], x3 = p[9];
    u32 h01, l01, h23, l23;
    split2(x0, x1, h01, l01);
    split2(x2, x3, h23, l23);
    dst[((size_t)ks * NT + nt) * 32 + lane]               = make_uint2(h01, h23);
    dst[((size_t)(KS + ks) * NT + nt) * 32 + lane]        = make_uint2(l01, l23);
}

__global__ void k_prep(const float* __restrict__ W10, const float* __restrict__ W20,
                       const float* __restrict__ W11, const float* __restrict__ W21)
{
    int i = blockIdx.x * 256 + threadIdx.x;
    if (i < 8192) {                       // layer0: KS=16, NT=16
        int lane = i & 31, nt = (i >> 5) & 15, ks = i >> 9;
        pack_frag(W10, g_w10f, ks, nt, lane, 16, 16, 256);
        pack_frag(W20, g_w20f, ks, nt, lane, 16, 16, 256);
    } else if (i < 10240) {               // layer1: KS=8, NT=8
        int j = i - 8192;
        int lane = j & 31, nt = (j >> 5) & 7, ks = j >> 8;
        pack_frag(W11, g_w11f, ks, nt, lane, 8, 8, 128);
        pack_frag(W21, g_w21f, ks, nt, lane, 8, 8, 128);
    }
}

// ============================================================================
// Tensor-core dual GEMM (bf16x3 compensated) via mma.sync:
//   Fout[r,c] = (A@W1^T)[r,c] + b1[c]+b2[c]
//   Hout[r,c] = (A@W1^T + (A*A)@W2^T)[r,c]
// MODE 0: A = concat(uE,iE) [N,256] -> g_F1,g_H0 (DOUT=128)
// MODE 1: A = g_F1 [N,128]          -> g_F2,g_H1 (DOUT=64)
// 8 warps, warp tile 32x32.
// ============================================================================
template<int BM, int DOUT, int KTOT, int MODE, int WM_N, int WN_N>
__global__ __launch_bounds__(256, 1) void k_gemm_mma(
    const float* __restrict__ uE, const float* __restrict__ iE,
    const float* __restrict__ b1, const float* __restrict__ b2)
{
    constexpr int SR = 72;                 // bf16 row stride (144B)
    constexpr int ABUF = BM * SR;          // bf16 per variant
    constexpr int KS = KTOT / 16;
    constexpr int NT = DOUT / 8;
    extern __shared__ __align__(16) char smem[];
    __nv_bfloat16* sA = (__nv_bfloat16*)smem;
    const u32 sbase = smem_u32(smem);

    const uint2* __restrict__ w1f = (MODE == 0) ? g_w10f : g_w11f;
    const uint2* __restrict__ w2f = (MODE == 0) ? g_w20f : g_w21f;
    float* __restrict__ Fout = (MODE == 0) ? g_F1 : g_F2;
    float* __restrict__ Hout = (MODE == 0) ? g_H0 : g_H1;

    const int t = threadIdx.x, wid = t >> 5, lane = t & 31;
    const int wm = wid / WN_N, wn = wid % WN_N;
    const int row0 = blockIdx.x * BM;

    float acc1[2][4][4], acc2[2][4][4];
#pragma unroll
    for (int mt = 0; mt < 2; mt++)
#pragma unroll
        for (int j = 0; j < 4; j++)
#pragma unroll
            for (int q = 0; q < 4; q++) { acc1[mt][j][q] = 0.f; acc2[mt][j][q] = 0.f; }

    for (int kc = 0; kc < KTOT / 64; kc++) {
        const int k0 = kc * 64;
        __syncthreads();
        // ---- stage A chunk: fp32 -> {hi, lo, sqhi, sqlo} bf16 ----
#pragma unroll
        for (int it = 0; it < BM / 16; it++) {
            int fid = t + it * 256;
            int r = fid >> 4;
            int c4 = (fid & 15) * 4;
            int gr = row0 + r;
            float4 v = make_float4(0.f, 0.f, 0.f, 0.f);
            if (gr < NTOT) {
                const float* src;
                if (MODE == 0) src = (gr < U_NUM) ? uE + (size_t)gr * 256
                                                  : iE + (size_t)(gr - U_NUM) * 256;
                else           src = g_F1 + (size_t)gr * 128;
                v = *(const float4*)(src + k0 + c4);
            }
            u32 h01, l01, h23, l23, sh01, sl01, sh23, sl23;
            split2(v.x, v.y, h01, l01);
            split2(v.z, v.w, h23, l23);
            split2(v.x * v.x, v.y * v.y, sh01, sl01);
            split2(v.z * v.z, v.w * v.w, sh23, sl23);
            int off = r * SR + c4;
            *(uint2*)(sA + off)            = make_uint2(h01, h23);
            *(uint2*)(sA + ABUF + off)     = make_uint2(l01, l23);
            *(uint2*)(sA + 2 * ABUF + off) = make_uint2(sh01, sh23);
            *(uint2*)(sA + 3 * ABUF + off) = make_uint2(sl01, sl23);
        }
        __syncthreads();

#pragma unroll
        for (int ks4 = 0; ks4 < 4; ks4++) {
            const int ks = kc * 4 + ks4;
            // B fragments (global, fragment-packed, L1-hot)
            uint2 bw1[2][4], bw2[2][4];
#pragma unroll
            for (int v = 0; v < 2; v++)
#pragma unroll
                for (int j = 0; j < 4; j++) {
                    int nt = wn * 4 + j;
                    size_t idx = ((size_t)(v * KS + ks) * NT + nt) * 32 + lane;
                    bw1[v][j] = __ldg(w1f + idx);
                    bw2[v][j] = __ldg(w2f + idx);
                }
            // A fragments via ldmatrix
            u32 a[4][2][4];
            const int arow = (lane & 15);
            const int kcol = ks4 * 16 + (lane >> 4) * 8;
#pragma unroll
            for (int v = 0; v < 4; v++)
#pragma unroll
                for (int mt = 0; mt < 2; mt++) {
                    int row = wm * 32 + mt * 16 + arow;
                    u32 addr = sbase + (u32)((v * ABUF + row * SR + kcol) * 2);
                    ldm4(a[v][mt], addr);
                }
            // 6 compensated products
#pragma unroll
            for (int mt = 0; mt < 2; mt++)
#pragma unroll
                for (int j = 0; j < 4; j++) {
                    mma16816(acc1[mt][j], a[0][mt], bw1[0][j]);  // Ahi*W1hi
                    mma16816(acc1[mt][j], a[0][mt], bw1[1][j]);  // Ahi*W1lo
                    mma16816(acc1[mt][j], a[1][mt], bw1[0][j]);  // Alo*W1hi
                    mma16816(acc2[mt][j], a[2][mt], bw2[0][j]);  // Shi*W2hi
                    mma16816(acc2[mt][j], a[2][mt], bw2[1][j]);  // Shi*W2lo
                    mma16816(acc2[mt][j], a[3][mt], bw2[0][j]);  // Slo*W2hi
                }
        }
    }

    // ---- epilogue ----
    const int r_base = row0 + wm * 32 + (lane >> 2);
    const int c_base = wn * 32 + (lane & 3) * 2;
#pragma unroll
    for (int mt = 0; mt < 2; mt++)
#pragma unroll
        for (int j = 0; j < 4; j++) {
            int c = c_base + j * 8;
            float bs0 = __ldg(b1 + c) + __ldg(b2 + c);
            float bs1 = __ldg(b1 + c + 1) + __ldg(b2 + c + 1);
#pragma unroll
            for (int half = 0; half < 2; half++) {
                int r = r_base + mt * 16 + half * 8;
                if (r < NTOT) {
                    float a0 = acc1[mt][j][half * 2], a1 = acc1[mt][j][half * 2 + 1];
                    float2 f = make_float2(a0 + bs0, a1 + bs1);
                    float2 h = make_float2(a0 + acc2[mt][j][half * 2],
                                           a1 + acc2[mt][j][half * 2 + 1]);
                    *(float2*)(Fout + (size_t)r * DOUT + c) = f;
                    *(float2*)(Hout + (size_t)r * DOUT + c) = h;
                }
            }
        }
}

// ============================================================================
// SpMM scatter: F[row] += val * H[col]
// ============================================================================
__global__ void k_spmm128(const int* __restrict__ er, const int* __restrict__ ec,
                          const float* __restrict__ ev, int nnz)
{
    int w = (blockIdx.x * blockDim.x + threadIdx.x) >> 5;
    int lane = threadIdx.x & 31;
    if (w >= nnz) return;
    int r = __ldg(er + w), c = __ldg(ec + w);
    float v = __ldg(ev + w);
    float4 x = *(const float4*)(g_H0 + (size_t)c * 128 + lane * 4);
    red4(g_F1 + (size_t)r * 128 + lane * 4, v * x.x, v * x.y, v * x.z, v * x.w);
}

__global__ void k_spmm64(const int* __restrict__ er, const int* __restrict__ ec,
                         const float* __restrict__ ev, int nnz)
{
    int idx = blockIdx.x * blockDim.x + threadIdx.x;
    int e = idx >> 4;
    int l = idx & 15;
    if (e >= nnz) return;
    int r = __ldg(er + e), c = __ldg(ec + e);
    float v = __ldg(ev + e);
    float4 x = *(const float4*)(g_H1 + (size_t)c * 64 + l * 4);
    red4(g_F2 + (size_t)r * 64 + l * 4, v * x.x, v * x.y, v * x.z, v * x.w);
}

// ============================================================================
// Fused MLP head
// ============================================================================
__global__ __launch_bounds__(256) void k_mlp(
    const int* __restrict__ uIdx, const int* __restrict__ itIdx,
    const float* __restrict__ uE, const float* __restrict__ iE,
    const float* __restrict__ T1W, const float* __restrict__ T1b,
    const float* __restrict__ T2W, const float* __restrict__ T2b,
    const float* __restrict__ T3W, const float* __restrict__ T3b,
    float* __restrict__ out, int B)
{
    __shared__ float As[32][68];
    __shared__ float Bs[32][64];
    __shared__ float Hs[64][65];
    __shared__ float T2s[32][64];
    __shared__ int   su[64], si[64];
    __shared__ float part[4][64];

    const int t = threadIdx.x;
    const int rb = blockIdx.x * 64;
    if (t < 64) {
        int br = rb + t;
        su[t] = (br < B) ? uIdx[br] : 0;
        si[t] = (br < B) ? itIdx[br] : 0;
    }
#pragma unroll
    for (int i = 0; i < 2; i++) {
        int idx = t + i * 256;
        ((float4*)&T2s[0][0])[idx] = ((const float4*)T2W)[idx];
    }
    __syncthreads();

    const int ty = t >> 4, tx = t & 15;
    u64 acc[4][2];
#pragma unroll
    for (int i = 0; i < 4; i++) { acc[i][0] = 0ull; acc[i][1] = 0ull; }

    for (int kc = 0; kc < 28; kc++) {
        int kb = kc * 32;
        const float* src; int stride, off, radd; bool useU;
        if      (kb < 256) { src = uE;   stride = 256; off = kb;       useU = true;  radd = 0; }
        else if (kb < 384) { src = g_F1; stride = 128; off = kb - 256; useU = true;  radd = 0; }
        else if (kb < 448) { src = g_F2; stride = 64;  off = kb - 384; useU = true;  radd = 0; }
        else if (kb < 704) { src = iE;   stride = 256; off = kb - 448; useU = false; radd = 0; }
        else if (kb < 832) { src = g_F1; stride = 128; off = kb - 704; useU = false; radd = U_NUM; }
        else               { src = g_F2; stride = 64;  off = kb - 832; useU = false; radd = U_NUM; }
        __syncthreads();
#pragma unroll
        for (int i = 0; i < 2; i++) {
            int idx = t + i * 256;
            int r = idx >> 3, kq = (idx & 7) * 4;
            int rowi = (useU ? su[r] : si[r]) + radd;
            float4 a = *(const float4*)(src + (size_t)rowi * stride + off + kq);
            As[kq + 0][r] = a.x; As[kq + 1][r] = a.y;
            As[kq + 2][r] = a.z; As[kq + 3][r] = a.w;
            float4 wv = *(const float4*)(T1W + (size_t)r * 896 + kb + kq);
            Bs[kq + 0][r] = wv.x; Bs[kq + 1][r] = wv.y;
            Bs[kq + 2][r] = wv.z; Bs[kq + 3][r] = wv.w;
        }
        __syncthreads();
#pragma unroll
        for (int k = 0; k < 32; k++) {
            float4 af = *(const float4*)&As[k][ty * 4];
            u64 ad[4];
            ad[0] = pack2(af.x, af.x); ad[1] = pack2(af.y, af.y);
            ad[2] = pack2(af.z, af.z); ad[3] = pack2(af.w, af.w);
            ulonglong2 bp = *(const ulonglong2*)&Bs[k][tx * 4];
#pragma unroll
            for (int i = 0; i < 4; i++) {
                acc[i][0] = fma2(ad[i], bp.x, acc[i][0]);
                acc[i][1] = fma2(ad[i], bp.y, acc[i][1]);
            }
        }
    }

    float t1bv[4];
#pragma unroll
    for (int j = 0; j < 4; j++) t1bv[j] = T1b[tx * 4 + j];
#pragma unroll
    for (int i = 0; i < 4; i++) {
#pragma unroll
        for (int j = 0; j < 2; j++) {
            float lo, hi;
            unpack2(acc[i][j], lo, hi);
            Hs[ty * 4 + i][tx * 4 + 2 * j]     = fmaxf(lo + t1bv[2 * j], 0.f);
            Hs[ty * 4 + i][tx * 4 + 2 * j + 1] = fmaxf(hi + t1bv[2 * j + 1], 0.f);
        }
    }
    __syncthreads();

    {
        int r = t & 63, g = t >> 6;
        float p = 0.f;
#pragma unroll
        for (int j = 0; j < 8; j++) {
            int c2 = g * 8 + j;
            float s = T2b[c2];
#pragma unroll
            for (int k = 0; k < 64; k++) s += Hs[r][k] * T2s[c2][k];
            s = fmaxf(s, 0.f);
            p += s * T3W[c2];
        }
        part[g][r] = p;
    }
    __syncthreads();
    if (t < 64) {
        int br = rb + t;
        if (br < B)
            out[br] = part[0][t] + part[1][t] + part[2][t] + part[3][t] + T3b[0];
    }
}

// ============================================================================
extern "C" void kernel_launch(void* const* d_in, const int* in_sizes, int n_in,
                              void* d_out, int out_size)
{
    const int*   userIdx = (const int*)d_in[0];
    const int*   itemIdx = (const int*)d_in[1];
    const int*   er      = (const int*)d_in[2];
    const int*   ec      = (const int*)d_in[3];
    const float* ev      = (const float*)d_in[4];
    const float* uE      = (const float*)d_in[5];
    const float* iE      = (const float*)d_in[6];
    const float* W1_0    = (const float*)d_in[7];
    const float* b1_0    = (const float*)d_in[8];
    const float* W2_0    = (const float*)d_in[9];
    const float* b2_0    = (const float*)d_in[10];
    const float* W1_1    = (const float*)d_in[11];
    const float* b1_1    = (const float*)d_in[12];
    const float* W2_1    = (const float*)d_in[13];
    const float* b2_1    = (const float*)d_in[14];
    const float* T1W     = (const float*)d_in[15];
    const float* T1b     = (const float*)d_in[16];
    const float* T2W     = (const float*)d_in[17];
    const float* T2b     = (const float*)d_in[18];
    const float* T3W     = (const float*)d_in[19];
    const float* T3b     = (const float*)d_in[20];
    float* out = (float*)d_out;

    const int B   = in_sizes[0];
    const int nnz = in_sizes[2];

    constexpr int SMEM0 = 4 * 64 * 72 * 2;    // 36864
    constexpr int SMEM1 = 4 * 128 * 72 * 2;   // 73728
    static bool attr_done = false;
    if (!attr_done) {
        cudaFuncSetAttribute((const void*)k_gemm_mma<64, 128, 256, 0, 2, 4>,
                             cudaFuncAttributeMaxDynamicSharedMemorySize, SMEM0);
        cudaFuncSetAttribute((const void*)k_gemm_mma<128, 64, 128, 1, 4, 2>,
                             cudaFuncAttributeMaxDynamicSharedMemorySize, SMEM1);
        attr_done = true;
    }

    k_prep<<<40, 256>>>(W1_0, W2_0, W1_1, W2_1);

    k_gemm_mma<64, 128, 256, 0, 2, 4><<<(NTOT + 63) / 64, 256, SMEM0>>>(uE, iE, b1_0, b2_0);

    {
        long long thr = (long long)nnz * 32;
        int blocks = (int)((thr + 255) / 256);
        k_spmm128<<<blocks, 256>>>(er, ec, ev, nnz);
    }

    k_gemm_mma<128, 64, 128, 1, 4, 2><<<(NTOT + 127) / 128, 256, SMEM1>>>(uE, iE, b1_1, b2_1);

    {
        long long thr = (long long)nnz * 16;
        int blocks = (int)((thr + 255) / 256);
        k_spmm64<<<blocks, 256>>>(er, ec, ev, nnz);
    }

    k_mlp<<<(B + 63) / 64, 256>>>(userIdx, itemIdx, uE, iE,
                                  T1W, T1b, T2W, T2b, T3W, T3b, out, B);
}